// round 1
// baseline (speedup 1.0000x reference)
#include <cuda_runtime.h>
#include <cstdint>
#include <math.h>

// Problem constants (fixed shapes for this problem instance)
#define Bv 4
#define Lv 2048
#define Kv 32
#define FD 416   // 16 pos + 25*16 rbf
#define CD 128

// Scratch (allocation-free rule: __device__ globals)
__device__ float g_atoms[Bv*Lv*5*3];   // [b][l][atom 0..4][xyz], atoms = N,Ca,C,O,Cb
__device__ float g_ca[Bv*Lv*3];        // Ca only, contiguous for distance kernel
__device__ int   g_eidx[Bv*Lv*Kv];
__device__ float g_dn[Bv*Lv*Kv];       // D_neighbors (= selected D_adjust)

__constant__ int c_PA[24] = {0,2,3,4,1,1,1,1,0,0,0,4,4,3,0,2,3,4,2,3,4,2,3,2};
__constant__ int c_PB[24] = {0,2,3,4,0,2,3,4,2,3,4,2,3,2,1,1,1,1,0,0,0,4,4,3};

// ---------------------------------------------------------------------------
// Kernel 1: build atom table (N, Ca, C, O, Cb)
// ---------------------------------------------------------------------------
__global__ void k1_atoms(const float* __restrict__ X) {
    int i = blockIdx.x * blockDim.x + threadIdx.x;
    if (i >= Bv*Lv) return;
    const float* x = X + (size_t)i * 12;
    float Nx=x[0],Ny=x[1],Nz=x[2];
    float Ax=x[3],Ay=x[4],Az=x[5];
    float Cx=x[6],Cy=x[7],Cz=x[8];
    float Ox=x[9],Oy=x[10],Oz=x[11];
    float bx=Ax-Nx, by=Ay-Ny, bz=Az-Nz;
    float cx=Cx-Ax, cy=Cy-Ay, cz=Cz-Az;
    float ax=by*cz-bz*cy, ay=bz*cx-bx*cz, az=bx*cy-by*cx;
    float Cbx = -0.58273431f*ax + 0.56802827f*bx - 0.54067466f*cx + Ax;
    float Cby = -0.58273431f*ay + 0.56802827f*by - 0.54067466f*cy + Ay;
    float Cbz = -0.58273431f*az + 0.56802827f*bz - 0.54067466f*cz + Az;
    float* p = g_atoms + (size_t)i * 15;
    p[0]=Nx; p[1]=Ny; p[2]=Nz;
    p[3]=Ax; p[4]=Ay; p[5]=Az;
    p[6]=Cx; p[7]=Cy; p[8]=Cz;
    p[9]=Ox; p[10]=Oy; p[11]=Oz;
    p[12]=Cbx; p[13]=Cby; p[14]=Cbz;
    g_ca[i*3+0]=Ax; g_ca[i*3+1]=Ay; g_ca[i*3+2]=Az;
}

// ---------------------------------------------------------------------------
// Kernel 2: per-row distances + top-K (ascending, ties -> lower index, exactly
// matching jax.lax.top_k(-D_adjust)). One block (256 threads) per (b,i).
// Key = (float_bits(D_adjust) << 32) | j  (D_adjust >= 0 so bits are monotone).
// ---------------------------------------------------------------------------
__device__ __forceinline__ unsigned long long umin64(unsigned long long a, unsigned long long b) {
    return a < b ? a : b;
}

__global__ void k2_topk(const float* __restrict__ mask) {
    extern __shared__ char smem_raw[];
    float* ca_s = (float*)smem_raw;                       // Lv*3 floats
    float* d_s  = ca_s + Lv*3;                            // Lv floats
    unsigned long long* key_s = (unsigned long long*)(d_s + Lv);  // Lv u64 (32KB offset: aligned)

    __shared__ float s_red[8];
    __shared__ unsigned long long s_wmin[8];
    __shared__ unsigned long long s_chosen;
    __shared__ float s_dmax;

    int row = blockIdx.x;            // b*Lv + i
    int b   = row >> 11;             // Lv = 2048
    int tid = threadIdx.x;           // 256 threads

    const float* cab = g_ca + (size_t)b * Lv * 3;
    for (int idx = tid; idx < Lv*3; idx += 256) ca_s[idx] = cab[idx];
    __syncthreads();

    int li = row & (Lv-1);
    float xi = ca_s[li*3+0], yi = ca_s[li*3+1], zi = ca_s[li*3+2];
    float mi = mask[row];
    const float* mb = mask + (size_t)b * Lv;

    float lmax = 0.0f;
    for (int j = tid; j < Lv; j += 256) {
        float dx = xi - ca_s[j*3+0];
        float dy = yi - ca_s[j*3+1];
        float dz = zi - ca_s[j*3+2];
        float d  = sqrtf(dx*dx + dy*dy + dz*dz + 1e-6f);
        float D  = mi * mb[j] * d;
        d_s[j] = D;
        lmax = fmaxf(lmax, D);
    }
    // block max
    #pragma unroll
    for (int o = 16; o; o >>= 1) lmax = fmaxf(lmax, __shfl_down_sync(0xffffffffu, lmax, o));
    if ((tid & 31) == 0) s_red[tid >> 5] = lmax;
    __syncthreads();
    if (tid == 0) {
        float m = s_red[0];
        #pragma unroll
        for (int w = 1; w < 8; w++) m = fmaxf(m, s_red[w]);
        s_dmax = m;
    }
    __syncthreads();
    float Dmax = s_dmax;

    for (int j = tid; j < Lv; j += 256) {
        float m2 = mi * mb[j];
        float Dadj = d_s[j] + (1.0f - m2) * Dmax;
        key_s[j] = (((unsigned long long)__float_as_uint(Dadj)) << 32) | (unsigned)j;
    }
    __syncthreads();

    // each thread owns contiguous slots [tid*8, tid*8+8)
    int base = tid * 8;
    unsigned long long lmin = ~0ULL;
    #pragma unroll
    for (int s = 0; s < 8; s++) lmin = umin64(lmin, key_s[base + s]);

    for (int r = 0; r < Kv; r++) {
        unsigned long long w = lmin;
        #pragma unroll
        for (int o = 16; o; o >>= 1) {
            unsigned long long v = __shfl_down_sync(0xffffffffu, w, o);
            w = umin64(w, v);
        }
        if ((tid & 31) == 0) s_wmin[tid >> 5] = w;
        __syncthreads();
        if (tid == 0) {
            unsigned long long m = s_wmin[0];
            #pragma unroll
            for (int q = 1; q < 8; q++) m = umin64(m, s_wmin[q]);
            s_chosen = m;
        }
        __syncthreads();
        unsigned long long ch = s_chosen;
        int j = (int)(unsigned)(ch & 0xffffffffu);
        if (tid == 0) {
            g_eidx[(size_t)row*Kv + r] = j;
            g_dn[(size_t)row*Kv + r]   = __uint_as_float((unsigned)(ch >> 32));
        }
        if ((j >> 3) == tid) {
            key_s[j] = ~0ULL;
            lmin = ~0ULL;
            #pragma unroll
            for (int s = 0; s < 8; s++) lmin = umin64(lmin, key_s[base + s]);
        }
        __syncthreads();
    }
}

// ---------------------------------------------------------------------------
// Kernel 3: per (b,i): build F[32][416] = [E_pos(16) | R0(16) | 24 x RBF16],
// GEMM F @ W_edge (416x128), LayerNorm(128), write E (+ E_idx tail).
// 256 threads: 8 warps; warp w computes rows 4w..4w+3, lane -> 4 columns.
// ---------------------------------------------------------------------------
__global__ void k3_edge(const int* __restrict__ ridx, const int* __restrict__ chl,
                        const float* __restrict__ Wpos, const float* __restrict__ bpos,
                        const float* __restrict__ Wedge,
                        const float* __restrict__ gamma, const float* __restrict__ beta,
                        float* __restrict__ out, int write_idx) {
    extern __shared__ float smem[];
    float* F   = smem;                 // 32*416
    float* qa  = F + Kv*FD;            // 16 (15 used)
    float* nbA = qa + 16;              // 32*15
    int*   jv  = (int*)(nbA + Kv*15);  // 32
    float* Dn  = (float*)(jv + Kv);    // 32
    int*  dpos = (int*)(Dn + Kv);      // 32

    int row = blockIdx.x;            // b*Lv + i
    int b   = row >> 11;
    int tid = threadIdx.x;

    if (tid < Kv) {
        int j = g_eidx[(size_t)row*Kv + tid];
        jv[tid] = j;
        Dn[tid] = g_dn[(size_t)row*Kv + tid];
        int off = ridx[row] - ridx[(size_t)b*Lv + j];
        int ech = (chl[row] == chl[(size_t)b*Lv + j]) ? 1 : 0;
        int d = off + 32;
        d = d < 0 ? 0 : (d > 64 ? 64 : d);
        dpos[tid] = ech ? d : 65;
    }
    if (tid < 15) qa[tid] = g_atoms[(size_t)row*15 + tid];
    __syncthreads();

    // gather neighbor atoms (32 neighbors x 5 atoms x 3)
    for (int t = tid; t < Kv*15; t += 256) {
        int k = t / 15, r2 = t % 15;
        nbA[t] = g_atoms[((size_t)b*Lv + jv[k])*15 + r2];
    }
    // positional embedding: F[k][0..15]
    for (int t = tid; t < Kv*16; t += 256) {
        int k = t >> 4, c = t & 15;
        F[k*FD + c] = Wpos[dpos[k]*16 + c] + bpos[c];
    }
    __syncthreads();

    // RBF groups: g=0 -> D_neighbors, g=1..24 -> atom-pair distances
    const float inv_sigma = 0.8f; // 1 / 1.25
    for (int t = tid; t < Kv*25; t += 256) {
        int k = t / 25, g = t % 25;
        float Dv;
        if (g == 0) {
            Dv = Dn[k];
        } else {
            int p = g - 1;
            const float* A  = qa  + c_PA[p]*3;
            const float* Bp = nbA + k*15 + c_PB[p]*3;
            float dx = A[0]-Bp[0], dy = A[1]-Bp[1], dz = A[2]-Bp[2];
            Dv = sqrtf(dx*dx + dy*dy + dz*dz + 1e-6f);
        }
        float* dst = F + k*FD + 16 + g*16;
        #pragma unroll
        for (int m = 0; m < 16; m++) {
            float mu = 2.0f + (float)m * (4.0f/3.0f);
            float z = (Dv - mu) * inv_sigma;
            dst[m] = expf(-(z*z));
        }
    }
    __syncthreads();

    // GEMM: rows = edges (32), cols = 128 outputs
    int warp = tid >> 5, lane = tid & 31;
    int c0 = lane * 4;
    float acc[4][4];
    #pragma unroll
    for (int r = 0; r < 4; r++) {
        acc[r][0]=0.f; acc[r][1]=0.f; acc[r][2]=0.f; acc[r][3]=0.f;
    }
    const float* Fw = F + (warp*4)*FD;
    #pragma unroll 4
    for (int f = 0; f < FD; f++) {
        float4 wv = *(const float4*)(Wedge + (size_t)f*CD + c0);
        #pragma unroll
        for (int r = 0; r < 4; r++) {
            float fv = Fw[r*FD + f];
            acc[r][0] = fmaf(fv, wv.x, acc[r][0]);
            acc[r][1] = fmaf(fv, wv.y, acc[r][1]);
            acc[r][2] = fmaf(fv, wv.z, acc[r][2]);
            acc[r][3] = fmaf(fv, wv.w, acc[r][3]);
        }
    }

    // LayerNorm per row (128 values spread across the warp, 4 per lane)
    float4 gv = *(const float4*)(gamma + c0);
    float4 bv = *(const float4*)(beta + c0);
    #pragma unroll
    for (int r = 0; r < 4; r++) {
        float s = acc[r][0] + acc[r][1] + acc[r][2] + acc[r][3];
        #pragma unroll
        for (int o = 16; o; o >>= 1) s += __shfl_xor_sync(0xffffffffu, s, o);
        float mu = s * (1.0f/128.0f);
        float d0 = acc[r][0]-mu, d1 = acc[r][1]-mu, d2 = acc[r][2]-mu, d3 = acc[r][3]-mu;
        float ss = d0*d0 + d1*d1 + d2*d2 + d3*d3;
        #pragma unroll
        for (int o = 16; o; o >>= 1) ss += __shfl_xor_sync(0xffffffffu, ss, o);
        float var = ss * (1.0f/128.0f);
        float inv = 1.0f / sqrtf(var + 1e-5f);
        int k = warp*4 + r;
        float4 res;
        res.x = d0*inv*gv.x + bv.x;
        res.y = d1*inv*gv.y + bv.y;
        res.z = d2*inv*gv.z + bv.z;
        res.w = d3*inv*gv.w + bv.w;
        *(float4*)(out + (((size_t)row*Kv + k)*CD + c0)) = res;
    }

    if (write_idx && tid < Kv) {
        out[(size_t)Bv*Lv*Kv*CD + (size_t)row*Kv + tid] = (float)jv[tid];
    }
}

// ---------------------------------------------------------------------------
// Launch
// ---------------------------------------------------------------------------
extern "C" void kernel_launch(void* const* d_in, const int* in_sizes, int n_in,
                              void* d_out, int out_size) {
    const float* X     = (const float*)d_in[0];
    const float* mask  = (const float*)d_in[1];
    const int*   ridx  = (const int*)  d_in[2];
    const int*   chl   = (const int*)  d_in[3];
    const float* Wpos  = (const float*)d_in[4];
    const float* bpos  = (const float*)d_in[5];
    const float* Wedge = (const float*)d_in[6];
    const float* gamma = (const float*)d_in[7];
    const float* beta  = (const float*)d_in[8];
    float* out = (float*)d_out;

    const int k2_smem = (Lv*3 + Lv)*4 + Lv*8;                 // 49152 B
    const int k3_smem = (Kv*FD + 16 + Kv*15 + Kv*3) * 4;      // 55616 B
    cudaFuncSetAttribute(k2_topk, cudaFuncAttributeMaxDynamicSharedMemorySize, k2_smem);
    cudaFuncSetAttribute(k3_edge, cudaFuncAttributeMaxDynamicSharedMemorySize, k3_smem);

    k1_atoms<<<(Bv*Lv + 255)/256, 256>>>(X);
    k2_topk<<<Bv*Lv, 256, k2_smem>>>(mask);

    long long e_elems = (long long)Bv*Lv*Kv*CD;
    int write_idx = ((long long)out_size >= e_elems + (long long)Bv*Lv*Kv) ? 1 : 0;
    k3_edge<<<Bv*Lv, 256, k3_smem>>>(ridx, chl, Wpos, bpos, Wedge, gamma, beta, out, write_idx);
}